// round 11
// baseline (speedup 1.0000x reference)
#include <cuda_runtime.h>

#define DD 11
#define DP 12
#define NTOK 49
#define NTOKP 52
#define SEQ 900
#define FFD 64
#define FFP 68
#define NT 512
#define NW 16

__device__ __forceinline__ float dot12(const float* __restrict__ a, const float* __restrict__ b) {
    float4 a0 = ((const float4*)a)[0], a1 = ((const float4*)a)[1], a2 = ((const float4*)a)[2];
    float4 b0 = ((const float4*)b)[0], b1 = ((const float4*)b)[1], b2 = ((const float4*)b)[2];
    float sx = a0.x * b0.x, sy = a0.y * b0.y, sz = a0.z * b0.z, sw = a0.w * b0.w;
    sx += a1.x * b1.x; sy += a1.y * b1.y; sz += a1.z * b1.z; sw += a1.w * b1.w;
    sx += a2.x * b2.x; sy += a2.y * b2.y; sz += a2.z * b2.z; sw += a2.w * b2.w;
    return (sx + sy) + (sz + sw);
}

__device__ __forceinline__ float dot12q(float4 q0, float4 q1, float4 q2, const float* __restrict__ b) {
    float4 b0 = ((const float4*)b)[0], b1 = ((const float4*)b)[1], b2 = ((const float4*)b)[2];
    float sx = q0.x * b0.x, sy = q0.y * b0.y, sz = q0.z * b0.z, sw = q0.w * b0.w;
    sx += q1.x * b1.x; sy += q1.y * b1.y; sz += q1.z * b1.z; sw += q1.w * b1.w;
    sx += q2.x * b2.x; sy += q2.y * b2.y; sz += q2.z * b2.z; sw += q2.w * b2.w;
    return (sx + sy) + (sz + sw);
}

__device__ __forceinline__ float dot52(const float* __restrict__ a, const float* __restrict__ b) {
    const float4* A = (const float4*)a;
    const float4* B = (const float4*)b;
    float sx = 0.f, sy = 0.f, sz = 0.f, sw = 0.f;
    #pragma unroll
    for (int i = 0; i < 13; i++) {
        float4 x = A[i], y = B[i];
        sx += x.x * y.x; sy += x.y * y.y; sz += x.z * y.z; sw += x.w * y.w;
    }
    return (sx + sy) + (sz + sw);
}

__device__ __forceinline__ float dot64(const float* __restrict__ a, const float* __restrict__ b) {
    const float4* A = (const float4*)a;
    const float4* B = (const float4*)b;
    float sx = 0.f, sy = 0.f, sz = 0.f, sw = 0.f;
    #pragma unroll
    for (int i = 0; i < 16; i++) {
        float4 x = A[i], y = B[i];
        sx += x.x * y.x; sy += x.y * y.y; sz += x.z * y.z; sw += x.w * y.w;
    }
    return (sx + sy) + (sz + sw);
}

__device__ __forceinline__ float wsum(float v) {
    #pragma unroll
    for (int o = 16; o; o >>= 1) v += __shfl_xor_sync(0xffffffffu, v, o);
    return v;
}

__global__ __launch_bounds__(NT) void pve_kernel(
    const float* __restrict__ x,     // [10,16,16]
    const float* __restrict__ Wqkv,  // [33,11]
    const float* __restrict__ Wo,    // [11,11]
    const float* __restrict__ W1,    // [64,11]
    const float* __restrict__ W2,    // [11,64]
    const float* __restrict__ ln1,   // [11]
    const float* __restrict__ ln2,   // [11]
    float* __restrict__ out)         // [256,10,900]
{
    __shared__ __align__(16) float sWqkv[33 * DP];
    __shared__ __align__(16) float sWo[11 * DP];
    __shared__ __align__(16) float sW1[FFD * DP];
    __shared__ __align__(16) float sW2[11 * FFP];
    __shared__ float sLn1[32], sLn2[32];
    __shared__ __align__(16) float sX[50 * DP];
    __shared__ __align__(16) float sQ[50 * DP];
    __shared__ __align__(16) float sK[50 * DP];
    __shared__ __align__(16) float sVt[DD * NTOKP];
    __shared__ __align__(16) float sE[50 * NTOKP];
    __shared__ __align__(16) float sH[50 * FFP];   // per-row scratch: A (slots 0-11), then H (0-63)
    __shared__ __align__(16) float sX1[50 * DP];
    __shared__ __align__(16) float sO[50 * DP];

    const int tid  = threadIdx.x;
    const int wid  = tid >> 5;
    const int lane = tid & 31;
    const int b  = blockIdx.x;
    const int ph = b >> 4;
    const int pw = b & 15;

    // ================= phase A: stage weights (padded) + gather x + zero pads ====
    for (int i = tid; i < 33 * DP; i += NT) {
        const int r = i / DP, e = i - r * DP;
        sWqkv[i] = (e < DD) ? Wqkv[r * DD + e] : 0.f;
    }
    for (int i = tid; i < 11 * DP; i += NT) {
        const int r = i / DP, e = i - r * DP;
        sWo[i] = (e < DD) ? Wo[r * DD + e] : 0.f;
    }
    for (int i = tid; i < FFD * DP; i += NT) {
        const int r = i / DP, e = i - r * DP;
        sW1[i] = (e < DD) ? W1[r * DD + e] : 0.f;
    }
    for (int i = tid; i < 11 * FFP; i += NT) {
        const int r = i / FFP, k = i - r * FFP;
        if (k < FFD) sW2[i] = W2[r * FFD + k];
    }
    if (tid < 32) {
        sLn1[tid] = (tid < DD) ? ln1[tid] : 0.f;
        sLn2[tid] = (tid < DD) ? ln2[tid] : 0.f;
    }
    // token inputs (inline token id; row 49 = zero token)
    for (int idx = tid; idx < 50 * DP; idx += NT) {
        const int t = idx / DP, c = idx - t * DP;
        float v = 0.f;
        if (t < NTOK && c < DD) {
            const int i = t / 7, j = t - i * 7;
            const int hh = ph + i - 3, ww = pw + j - 3;
            const bool inb = ((unsigned)hh < 16u) && ((unsigned)ww < 16u);
            if (c < 10) v = inb ? x[c * 256 + hh * 16 + ww] : 0.f;
            else        v = inb ? 0.f : 1.f;
        }
        sX[idx] = v;
    }
    // zero pad slots: sQ/sK slot 11 per row; sVt tails 49-51
    for (int t = tid; t < 50; t += NT) { sQ[t * DP + DD] = 0.f; sK[t * DP + DD] = 0.f; }
    for (int i = tid; i < DD * 3; i += NT) {
        const int d = i / 3;
        sVt[d * NTOKP + NTOK + (i - d * 3)] = 0.f;
    }
    __syncthreads();

    // ================= phase B: QKV (50x33 dot-12s); q pre-scaled ================
    {
        const float scale = rsqrtf(11.f);
        for (int idx = tid; idx < 50 * 33; idx += NT) {
            const int row = idx / 33, col = idx - row * 33;
            const float a = dot12(&sX[row * DP], &sWqkv[col * DP]);
            const int p = col / DD, d = col - p * DD;
            if (p == 0)      sQ[row * DP + d] = a * scale;
            else if (p == 1) sK[row * DP + d] = a;
            else if (row < NTOK) sVt[d * NTOKP + row] = a;
        }
    }
    __syncthreads();

    // ================= phase C: per-row warp pipelines (no CTA barriers) =========
    for (int row = wid; row < 50; row += NW) {
        const float* qr = &sQ[row * DP];
        const float4 q0 = ((const float4*)qr)[0];
        const float4 q1 = ((const float4*)qr)[1];
        const float4 q2 = ((const float4*)qr)[2];

        // scores + exp: lane = key u, and u+32
        const int u2 = lane + 32;
        float e0 = __expf(dot12q(q0, q1, q2, &sK[lane * DP]));
        float e1 = 0.f;
        if (u2 < NTOK) e1 = __expf(dot12q(q0, q1, q2, &sK[u2 * DP]));
        float* Er = &sE[row * NTOKP];
        Er[lane] = e0;
        if (u2 < NTOKP) Er[u2] = (u2 < NTOK) ? e1 : 0.f;
        const float zinv = 1.f / (851.f + wsum(e0 + e1));
        __syncwarp();

        // A = E @ V^T : lane = dim d, into sH-row scratch
        float* scr = &sH[row * FFP];
        float a = 0.f;
        if (lane < DD) a = dot52(Er, &sVt[lane * NTOKP]);
        if (lane < DP) scr[lane] = a;     // lane 11 -> 0 pad
        __syncwarp();

        // Wo proj + residual
        float r = 0.f;
        if (lane < DD) r = sX[row * DP + lane] + dot12(&sWo[lane * DP], scr) * zinv;

        // LayerNorm1 (warp shuffles)
        float m = wsum(r) * (1.f / 11.f);
        float t = (lane < DD) ? (r - m) : 0.f;
        float rstd = rsqrtf(wsum(t * t) * (1.f / 11.f) + 1e-5f);
        const float x1v = t * rstd * sLn1[lane];   // 0 for lane >= 11
        if (lane < DP) sX1[row * DP + lane] = x1v;
        __syncwarp();

        // FF1: lane = f and f+32
        const float* x1r = &sX1[row * DP];
        const float h0 = fmaxf(dot12(&sW1[lane * DP], x1r), 0.f);
        const float h1 = fmaxf(dot12(&sW1[(lane + 32) * DP], x1r), 0.f);
        scr[lane] = h0;
        scr[lane + 32] = h1;
        __syncwarp();

        // FF2 + residual
        float y = 0.f;
        if (lane < DD) y = x1v + dot64(scr, &sW2[lane * FFP]);

        // LayerNorm2
        m = wsum(y) * (1.f / 11.f);
        t = (lane < DD) ? (y - m) : 0.f;
        rstd = rsqrtf(wsum(t * t) * (1.f / 11.f) + 1e-5f);
        if (lane < DP) sO[row * DP + lane] = t * rstd * sLn2[lane];
    }
    __syncthreads();

    // ================= phase D: output (broadcast fill, then window overwrite) ===
    float* ob = out + b * (10 * SEQ);
    for (int idx = tid; idx < 10 * (SEQ / 4); idx += NT) {
        const int c = idx / (SEQ / 4), q = idx - c * (SEQ / 4);
        const float z = sO[NTOK * DP + c];
        ((float4*)(ob + c * SEQ))[q] = make_float4(z, z, z, z);
    }
    __syncthreads();
    for (int idx = tid; idx < 10 * NTOK; idx += NT) {
        const int c = idx / NTOK, w = idx - c * NTOK;
        const int i = w / 7, j = w - i * 7;
        ob[c * SEQ + i * 30 + j] = sO[w * DP + c];
    }
}

extern "C" void kernel_launch(void* const* d_in, const int* in_sizes, int n_in,
                              void* d_out, int out_size) {
    const float* x    = (const float*)d_in[0];
    const float* Wqkv = (const float*)d_in[1];
    const float* Wo   = (const float*)d_in[2];
    const float* W1   = (const float*)d_in[3];
    const float* W2   = (const float*)d_in[4];
    const float* ln1  = (const float*)d_in[5];
    const float* ln2  = (const float*)d_in[6];
    float* out = (float*)d_out;
    pve_kernel<<<256, NT>>>(x, Wqkv, Wo, W1, W2, ln1, ln2, out);
}

// round 13
// speedup vs baseline: 1.2556x; 1.2556x over previous
#include <cuda_runtime.h>

#define DD 11
#define DP 12
#define NTOK 49
#define NTOKP 52
#define SEQ 900
#define FFD 64
#define FFP 68
#define NT 384

__device__ __forceinline__ float dot3f4(float4 a0, float4 a1, float4 a2,
                                        float4 b0, float4 b1, float4 b2) {
    float sx = a0.x * b0.x, sy = a0.y * b0.y, sz = a0.z * b0.z, sw = a0.w * b0.w;
    sx += a1.x * b1.x; sy += a1.y * b1.y; sz += a1.z * b1.z; sw += a1.w * b1.w;
    sx += a2.x * b2.x; sy += a2.y * b2.y; sz += a2.z * b2.z; sw += a2.w * b2.w;
    return (sx + sy) + (sz + sw);
}

__device__ __forceinline__ float dot12(const float* __restrict__ a, const float* __restrict__ b) {
    const float4* A = (const float4*)a;
    const float4* B = (const float4*)b;
    return dot3f4(A[0], A[1], A[2], B[0], B[1], B[2]);
}

__global__ __launch_bounds__(NT, 2) void pve_kernel(
    const float* __restrict__ x,     // [10,16,16]
    const float* __restrict__ Wqkv,  // [33,11]
    const float* __restrict__ Wo,    // [11,11]
    const float* __restrict__ W1,    // [64,11]
    const float* __restrict__ W2,    // [11,64]
    const float* __restrict__ ln1,   // [11]
    const float* __restrict__ ln2,   // [11]
    float* __restrict__ out)         // [256,10,900]
{
    __shared__ __align__(16) float sWqkv[33 * DP];
    __shared__ __align__(16) float sWo[11 * DP];
    __shared__ __align__(16) float sW1[FFD * DP];
    __shared__ __align__(16) float sW2[11 * FFP];
    __shared__ float sLn1[DD], sLn2[DD];
    __shared__ __align__(16) float sX[50 * DP];
    __shared__ __align__(16) float sQ[50 * DP];
    __shared__ __align__(16) float sK[50 * DP];
    __shared__ __align__(16) float sVt[DD * NTOKP];
    __shared__ __align__(16) float sE[50 * NTOKP];
    __shared__ __align__(16) float sA[50 * DP];
    __shared__ __align__(16) float sR[50 * DP];
    __shared__ __align__(16) float sX1[50 * DP];
    __shared__ __align__(16) float sH[50 * FFP];
    __shared__ __align__(16) float sO[50 * DP];
    __shared__ float sZinv[50];

    const int tid = threadIdx.x;
    const int b  = blockIdx.x;
    const int ph = b >> 4;
    const int pw = b & 15;

    // ================= A: stage weights (padded) + tokens + pads =================
    for (int i = tid; i < 33 * DP; i += NT) {
        const int r = i / DP, e = i - r * DP;
        sWqkv[i] = (e < DD) ? Wqkv[r * DD + e] : 0.f;
    }
    for (int i = tid; i < 11 * DP; i += NT) {
        const int r = i / DP, e = i - r * DP;
        sWo[i] = (e < DD) ? Wo[r * DD + e] : 0.f;
    }
    for (int i = tid; i < FFD * DP; i += NT) {
        const int r = i / DP, e = i - r * DP;
        sW1[i] = (e < DD) ? W1[r * DD + e] : 0.f;
    }
    for (int i = tid; i < 11 * FFP; i += NT) {
        const int r = i / FFP, k = i - r * FFP;
        if (k < FFD) sW2[i] = W2[r * FFD + k];
    }
    if (tid < DD) { sLn1[tid] = ln1[tid]; sLn2[tid] = ln2[tid]; }
    for (int idx = tid; idx < 50 * DP; idx += NT) {     // token inputs; row 49 = zero
        const int t = idx / DP, c = idx - t * DP;
        float v = 0.f;
        if (t < NTOK && c < DD) {
            const int i = t / 7, j = t - i * 7;
            const int hh = ph + i - 3, ww = pw + j - 3;
            const bool inb = ((unsigned)hh < 16u) && ((unsigned)ww < 16u);
            if (c < 10) v = inb ? x[c * 256 + hh * 16 + ww] : 0.f;
            else        v = inb ? 0.f : 1.f;
        }
        sX[idx] = v;
    }
    for (int t = tid; t < 50; t += NT) {                // pad slots
        sQ[t * DP + DD] = 0.f; sK[t * DP + DD] = 0.f; sA[t * DP + DD] = 0.f;
    }
    for (int i = tid; i < DD * 3; i += NT) {            // sVt tails u=49..51
        const int d = i / 3;
        sVt[d * NTOKP + NTOK + (i - d * 3)] = 0.f;
    }
    __syncthreads();

    // ================= B: QKV, tiled 2 rows x 3 cols (25x11 items) ===============
    {
        const float scale = rsqrtf(11.f);
        for (int idx = tid; idx < 25 * 11; idx += NT) {
            const int rp = idx / 11, ct = idx - rp * 11;
            const int r0 = rp * 2, r1 = r0 + 1;
            const float4* X0 = (const float4*)&sX[r0 * DP];
            const float4* X1 = (const float4*)&sX[r1 * DP];
            const float4 a0 = X0[0], a1 = X0[1], a2 = X0[2];
            const float4 b0 = X1[0], b1 = X1[1], b2 = X1[2];
            #pragma unroll 1
            for (int k = 0; k < 3; k++) {
                const int c = ct * 3 + k;
                const float4* W = (const float4*)&sWqkv[c * DP];
                const float4 w0 = W[0], w1 = W[1], w2 = W[2];
                const float s0 = dot3f4(a0, a1, a2, w0, w1, w2);
                const float s1 = dot3f4(b0, b1, b2, w0, w1, w2);
                if (c < DD) {
                    sQ[r0 * DP + c] = s0 * scale;
                    sQ[r1 * DP + c] = s1 * scale;
                } else if (c < 2 * DD) {
                    sK[r0 * DP + (c - DD)] = s0;
                    sK[r1 * DP + (c - DD)] = s1;
                } else {
                    const int d = c - 2 * DD;
                    if (r0 < NTOK) sVt[d * NTOKP + r0] = s0;
                    if (r1 < NTOK) sVt[d * NTOKP + r1] = s1;
                }
            }
        }
    }
    __syncthreads();

    // ================= C: E = exp(QK^T), tiled 2 q-rows x 4 keys (25x13) =========
    for (int idx = tid; idx < 25 * 13; idx += NT) {
        const int rp = idx / 13, kt = idx - rp * 13;
        const int r0 = rp * 2, r1 = r0 + 1;
        const float4* Q0 = (const float4*)&sQ[r0 * DP];
        const float4* Q1 = (const float4*)&sQ[r1 * DP];
        const float4 a0 = Q0[0], a1 = Q0[1], a2 = Q0[2];
        const float4 b0 = Q1[0], b1 = Q1[1], b2 = Q1[2];
        #pragma unroll 1
        for (int i = 0; i < 4; i++) {
            const int u = kt * 4 + i;
            float e0 = 0.f, e1 = 0.f;
            if (u < NTOK) {
                const float4* K = (const float4*)&sK[u * DP];
                const float4 k0 = K[0], k1 = K[1], k2 = K[2];
                e0 = __expf(dot3f4(a0, a1, a2, k0, k1, k2));
                e1 = __expf(dot3f4(b0, b1, b2, k0, k1, k2));
            }
            sE[r0 * NTOKP + u] = e0;
            sE[r1 * NTOKP + u] = e1;
        }
    }
    __syncthreads();

    // ================= D: A = E @ V^T (tiled 2x2, 25x6) + Z (50) =================
    for (int idx = tid; idx < 150 + 50; idx += NT) {
        if (idx < 150) {
            const int rp = idx / 6, dt = idx - rp * 6;
            const int r0 = rp * 2, r1 = r0 + 1;
            const int d0 = dt * 2, d1 = d0 + 1;
            const float4* E0 = (const float4*)&sE[r0 * NTOKP];
            const float4* E1 = (const float4*)&sE[r1 * NTOKP];
            const float4* V0 = (const float4*)&sVt[d0 * NTOKP];
            const float4* V1 = (const float4*)&sVt[((d1 < DD) ? d1 : d0) * NTOKP];
            float s00 = 0.f, s01 = 0.f, s10 = 0.f, s11 = 0.f;
            #pragma unroll
            for (int i = 0; i < 13; i++) {
                const float4 e0 = E0[i], e1 = E1[i];
                const float4 v0 = V0[i], v1 = V1[i];
                s00 += e0.x * v0.x + e0.y * v0.y + e0.z * v0.z + e0.w * v0.w;
                s01 += e0.x * v1.x + e0.y * v1.y + e0.z * v1.z + e0.w * v1.w;
                s10 += e1.x * v0.x + e1.y * v0.y + e1.z * v0.z + e1.w * v0.w;
                s11 += e1.x * v1.x + e1.y * v1.y + e1.z * v1.z + e1.w * v1.w;
            }
            sA[r0 * DP + d0] = s00;
            sA[r1 * DP + d0] = s10;
            if (d1 < DD) { sA[r0 * DP + d1] = s01; sA[r1 * DP + d1] = s11; }
        } else {
            const int r = idx - 150;
            float z = 851.f;
            const float4* E = (const float4*)&sE[r * NTOKP];
            #pragma unroll
            for (int i = 0; i < 13; i++) {
                const float4 v = E[i];
                z += (v.x + v.y) + (v.z + v.w);
            }
            sZinv[r] = 1.f / z;
        }
    }
    __syncthreads();

    // ================= E: Wo proj + residual (550 dot12) =========================
    for (int idx = tid; idx < 550; idx += NT) {
        const int r = idx / DD, d = idx - r * DD;
        sR[r * DP + d] = sX[r * DP + d] + dot12(&sWo[d * DP], &sA[r * DP]) * sZinv[r];
    }
    __syncthreads();

    // ---- LayerNorm1 (50 threads) ----
    if (tid < 50) {
        float m = 0.f;
        #pragma unroll
        for (int d = 0; d < DD; d++) m += sR[tid * DP + d];
        m *= (1.f / 11.f);
        float v = 0.f;
        #pragma unroll
        for (int d = 0; d < DD; d++) { const float t = sR[tid * DP + d] - m; v += t * t; }
        const float rstd = rsqrtf(v * (1.f / 11.f) + 1e-5f);
        #pragma unroll
        for (int d = 0; d < DD; d++)
            sX1[tid * DP + d] = (sR[tid * DP + d] - m) * rstd * sLn1[d];
        sX1[tid * DP + DD] = 0.f;
    }
    __syncthreads();

    // ================= F: FF1 + relu, tiled 2 rows x 4 f (25x16) =================
    for (int idx = tid; idx < 25 * 16; idx += NT) {
        const int rp = idx / 16, ft = idx - rp * 16;
        const int r0 = rp * 2, r1 = r0 + 1;
        const float4* X0 = (const float4*)&sX1[r0 * DP];
        const float4* X1p = (const float4*)&sX1[r1 * DP];
        const float4 a0 = X0[0], a1 = X0[1], a2 = X0[2];
        const float4 b0 = X1p[0], b1 = X1p[1], b2 = X1p[2];
        #pragma unroll 1
        for (int i = 0; i < 4; i++) {
            const int f = ft * 4 + i;
            const float4* W = (const float4*)&sW1[f * DP];
            const float4 w0 = W[0], w1 = W[1], w2 = W[2];
            sH[r0 * FFP + f] = fmaxf(dot3f4(a0, a1, a2, w0, w1, w2), 0.f);
            sH[r1 * FFP + f] = fmaxf(dot3f4(b0, b1, b2, w0, w1, w2), 0.f);
        }
    }
    __syncthreads();

    // ================= G: FF2 + residual, tiled 2 rows x 2 d (25x6) ==============
    for (int idx = tid; idx < 150; idx += NT) {
        const int rp = idx / 6, dt = idx - rp * 6;
        const int r0 = rp * 2, r1 = r0 + 1;
        const int d0 = dt * 2, d1 = d0 + 1;
        const float4* H0 = (const float4*)&sH[r0 * FFP];
        const float4* H1 = (const float4*)&sH[r1 * FFP];
        const float4* W0 = (const float4*)&sW2[d0 * FFP];
        const float4* W1p = (const float4*)&sW2[((d1 < DD) ? d1 : d0) * FFP];
        float s00 = 0.f, s01 = 0.f, s10 = 0.f, s11 = 0.f;
        #pragma unroll
        for (int i = 0; i < 16; i++) {
            const float4 h0 = H0[i], h1 = H1[i];
            const float4 w0 = W0[i], w1 = W1p[i];
            s00 += h0.x * w0.x + h0.y * w0.y + h0.z * w0.z + h0.w * w0.w;
            s01 += h0.x * w1.x + h0.y * w1.y + h0.z * w1.z + h0.w * w1.w;
            s10 += h1.x * w0.x + h1.y * w0.y + h1.z * w0.z + h1.w * w0.w;
            s11 += h1.x * w1.x + h1.y * w1.y + h1.z * w1.z + h1.w * w1.w;
        }
        sR[r0 * DP + d0] = sX1[r0 * DP + d0] + s00;
        sR[r1 * DP + d0] = sX1[r1 * DP + d0] + s10;
        if (d1 < DD) {
            sR[r0 * DP + d1] = sX1[r0 * DP + d1] + s01;
            sR[r1 * DP + d1] = sX1[r1 * DP + d1] + s11;
        }
    }
    __syncthreads();

    // ---- LayerNorm2 (50 threads) -> sO ----
    if (tid < 50) {
        float m = 0.f;
        #pragma unroll
        for (int d = 0; d < DD; d++) m += sR[tid * DP + d];
        m *= (1.f / 11.f);
        float v = 0.f;
        #pragma unroll
        for (int d = 0; d < DD; d++) { const float t = sR[tid * DP + d] - m; v += t * t; }
        const float rstd = rsqrtf(v * (1.f / 11.f) + 1e-5f);
        #pragma unroll
        for (int d = 0; d < DD; d++)
            sO[tid * DP + d] = (sR[tid * DP + d] - m) * rstd * sLn2[d];
    }
    __syncthreads();

    // ================= H: output (broadcast fill + window overwrite) =============
    float* ob = out + b * (10 * SEQ);
    for (int idx = tid; idx < 10 * (SEQ / 4); idx += NT) {
        const int c = idx / (SEQ / 4), q = idx - c * (SEQ / 4);
        const float z = sO[NTOK * DP + c];
        ((float4*)(ob + c * SEQ))[q] = make_float4(z, z, z, z);
    }
    __syncthreads();
    for (int idx = tid; idx < 10 * NTOK; idx += NT) {
        const int c = idx / NTOK, w = idx - c * NTOK;
        const int i = w / 7, j = w - i * 7;
        ob[c * SEQ + i * 30 + j] = sO[w * DP + c];
    }
}

extern "C" void kernel_launch(void* const* d_in, const int* in_sizes, int n_in,
                              void* d_out, int out_size) {
    const float* x    = (const float*)d_in[0];
    const float* Wqkv = (const float*)d_in[1];
    const float* Wo   = (const float*)d_in[2];
    const float* W1   = (const float*)d_in[3];
    const float* W2   = (const float*)d_in[4];
    const float* ln1  = (const float*)d_in[5];
    const float* ln2  = (const float*)d_in[6];
    float* out = (float*)d_out;
    pve_kernel<<<256, NT>>>(x, Wqkv, Wo, W1, W2, ln1, ln2, out);
}

// round 15
// speedup vs baseline: 1.3122x; 1.0451x over previous
#include <cuda_runtime.h>

#define DD 11
#define DP 12
#define NTOK 49
#define NTOKP 52
#define SEQ 900
#define FFD 64
#define FFP 68
#define NT 512

// ---- packed f32x2 helpers (sm_103a) ----
__device__ __forceinline__ unsigned long long ffma2(unsigned long long a,
                                                    unsigned long long b,
                                                    unsigned long long c) {
    unsigned long long d;
    asm("fma.rn.f32x2 %0, %1, %2, %3;" : "=l"(d) : "l"(a), "l"(b), "l"(c));
    return d;
}
__device__ __forceinline__ unsigned long long add2(unsigned long long a,
                                                   unsigned long long b) {
    unsigned long long d;
    asm("add.rn.f32x2 %0, %1, %2;" : "=l"(d) : "l"(a), "l"(b));
    return d;
}
__device__ __forceinline__ float unpack_add(unsigned long long a) {
    float lo, hi;
    asm("mov.b64 {%0, %1}, %2;" : "=f"(lo), "=f"(hi) : "l"(a));
    return lo + hi;
}

// dot of two 12-float (48B, 16B-aligned) vectors; b loaded here, a preloaded
__device__ __forceinline__ float dot12r(ulonglong2 a0, ulonglong2 a1, ulonglong2 a2,
                                        ulonglong2 b0, ulonglong2 b1, ulonglong2 b2) {
    unsigned long long s0 = ffma2(a0.x, b0.x, 0ULL);
    unsigned long long s1 = ffma2(a0.y, b0.y, 0ULL);
    s0 = ffma2(a1.x, b1.x, s0);
    s1 = ffma2(a1.y, b1.y, s1);
    s0 = ffma2(a2.x, b2.x, s0);
    s1 = ffma2(a2.y, b2.y, s1);
    return unpack_add(add2(s0, s1));
}

__device__ __forceinline__ float dot12p(const float* __restrict__ a,
                                        const float* __restrict__ b) {
    const ulonglong2* A = (const ulonglong2*)a;
    const ulonglong2* B = (const ulonglong2*)b;
    return dot12r(A[0], A[1], A[2], B[0], B[1], B[2]);
}

__global__ __launch_bounds__(NT, 2) void pve_kernel(
    const float* __restrict__ x,     // [10,16,16]
    const float* __restrict__ Wqkv,  // [33,11]
    const float* __restrict__ Wo,    // [11,11]
    const float* __restrict__ W1,    // [64,11]
    const float* __restrict__ W2,    // [11,64]
    const float* __restrict__ ln1,   // [11]
    const float* __restrict__ ln2,   // [11]
    float* __restrict__ out)         // [256,10,900]
{
    __shared__ __align__(16) float sWqkv[33 * DP];
    __shared__ __align__(16) float sWo[11 * DP];
    __shared__ __align__(16) float sW1[FFD * DP];
    __shared__ __align__(16) float sW2[11 * FFP];
    __shared__ float sLn1[DD], sLn2[DD];
    __shared__ __align__(16) float sX[50 * DP];
    __shared__ __align__(16) float sQ[50 * DP];
    __shared__ __align__(16) float sK[50 * DP];
    __shared__ __align__(16) float sVt[DD * NTOKP];
    __shared__ __align__(16) float sE[50 * NTOKP];
    __shared__ __align__(16) float sA[50 * DP];
    __shared__ __align__(16) float sR[50 * DP];
    __shared__ __align__(16) float sX1[50 * DP];
    __shared__ __align__(16) float sH[50 * FFP];
    __shared__ __align__(16) float sO[50 * DP];
    __shared__ float sZinv[50];

    const int tid = threadIdx.x;
    const int b  = blockIdx.x;
    const int ph = b >> 4;
    const int pw = b & 15;

    // ================= A: stage weights (padded) + tokens + pads =================
    for (int i = tid; i < 33 * DP; i += NT) {
        const int r = i / DP, e = i - r * DP;
        sWqkv[i] = (e < DD) ? Wqkv[r * DD + e] : 0.f;
    }
    for (int i = tid; i < 11 * DP; i += NT) {
        const int r = i / DP, e = i - r * DP;
        sWo[i] = (e < DD) ? Wo[r * DD + e] : 0.f;
    }
    for (int i = tid; i < FFD * DP; i += NT) {
        const int r = i / DP, e = i - r * DP;
        sW1[i] = (e < DD) ? W1[r * DD + e] : 0.f;
    }
    for (int i = tid; i < 11 * FFP; i += NT) {
        const int r = i / FFP, k = i - r * FFP;
        if (k < FFD) sW2[i] = W2[r * FFD + k];
    }
    if (tid < DD) { sLn1[tid] = ln1[tid]; sLn2[tid] = ln2[tid]; }
    for (int idx = tid; idx < 50 * DP; idx += NT) {     // token inputs; row 49 = zero
        const int t = idx / DP, c = idx - t * DP;
        float v = 0.f;
        if (t < NTOK && c < DD) {
            const int i = t / 7, j = t - i * 7;
            const int hh = ph + i - 3, ww = pw + j - 3;
            const bool inb = ((unsigned)hh < 16u) && ((unsigned)ww < 16u);
            if (c < 10) v = inb ? x[c * 256 + hh * 16 + ww] : 0.f;
            else        v = inb ? 0.f : 1.f;
        }
        sX[idx] = v;
    }
    for (int t = tid; t < 50; t += NT) {                // pad slots
        sQ[t * DP + DD] = 0.f; sK[t * DP + DD] = 0.f; sA[t * DP + DD] = 0.f;
    }
    for (int i = tid; i < DD * 3; i += NT) {            // sVt tails u=49..51
        const int d = i / 3;
        sVt[d * NTOKP + NTOK + (i - d * 3)] = 0.f;
    }
    __syncthreads();

    // ================= B: QKV, tiled 2 rows x 3 cols (25x11 items) ===============
    {
        const float scale = rsqrtf(11.f);
        for (int idx = tid; idx < 25 * 11; idx += NT) {
            const int rp = idx / 11, ct = idx - rp * 11;
            const int r0 = rp * 2, r1 = r0 + 1;
            const ulonglong2* X0 = (const ulonglong2*)&sX[r0 * DP];
            const ulonglong2* X1 = (const ulonglong2*)&sX[r1 * DP];
            const ulonglong2 a0 = X0[0], a1 = X0[1], a2 = X0[2];
            const ulonglong2 b0 = X1[0], b1 = X1[1], b2 = X1[2];
            #pragma unroll 1
            for (int k = 0; k < 3; k++) {
                const int c = ct * 3 + k;
                const ulonglong2* W = (const ulonglong2*)&sWqkv[c * DP];
                const ulonglong2 w0 = W[0], w1 = W[1], w2 = W[2];
                const float s0 = dot12r(a0, a1, a2, w0, w1, w2);
                const float s1 = dot12r(b0, b1, b2, w0, w1, w2);
                if (c < DD) {
                    sQ[r0 * DP + c] = s0 * scale;
                    sQ[r1 * DP + c] = s1 * scale;
                } else if (c < 2 * DD) {
                    sK[r0 * DP + (c - DD)] = s0;
                    sK[r1 * DP + (c - DD)] = s1;
                } else {
                    const int d = c - 2 * DD;
                    if (r0 < NTOK) sVt[d * NTOKP + r0] = s0;
                    if (r1 < NTOK) sVt[d * NTOKP + r1] = s1;
                }
            }
        }
    }
    __syncthreads();

    // ================= C: E = exp(QK^T), tiled 2 q-rows x 4 keys (25x13) =========
    for (int idx = tid; idx < 25 * 13; idx += NT) {
        const int rp = idx / 13, kt = idx - rp * 13;
        const int r0 = rp * 2, r1 = r0 + 1;
        const ulonglong2* Q0 = (const ulonglong2*)&sQ[r0 * DP];
        const ulonglong2* Q1 = (const ulonglong2*)&sQ[r1 * DP];
        const ulonglong2 a0 = Q0[0], a1 = Q0[1], a2 = Q0[2];
        const ulonglong2 b0 = Q1[0], b1 = Q1[1], b2 = Q1[2];
        #pragma unroll 1
        for (int i = 0; i < 4; i++) {
            const int u = kt * 4 + i;
            float e0 = 0.f, e1 = 0.f;
            if (u < NTOK) {
                const ulonglong2* K = (const ulonglong2*)&sK[u * DP];
                const ulonglong2 k0 = K[0], k1 = K[1], k2 = K[2];
                e0 = __expf(dot12r(a0, a1, a2, k0, k1, k2));
                e1 = __expf(dot12r(b0, b1, b2, k0, k1, k2));
            }
            sE[r0 * NTOKP + u] = e0;
            sE[r1 * NTOKP + u] = e1;
        }
    }
    __syncthreads();

    // ================= D: A = E @ V^T (tiled 2x2, 25x6) + Z (50) =================
    for (int idx = tid; idx < 150 + 50; idx += NT) {
        if (idx < 150) {
            const int rp = idx / 6, dt = idx - rp * 6;
            const int r0 = rp * 2, r1 = r0 + 1;
            const int d0 = dt * 2, d1 = d0 + 1;
            const ulonglong2* E0 = (const ulonglong2*)&sE[r0 * NTOKP];
            const ulonglong2* E1 = (const ulonglong2*)&sE[r1 * NTOKP];
            const ulonglong2* V0 = (const ulonglong2*)&sVt[d0 * NTOKP];
            const ulonglong2* V1 = (const ulonglong2*)&sVt[((d1 < DD) ? d1 : d0) * NTOKP];
            unsigned long long s00 = 0ULL, s01 = 0ULL, s10 = 0ULL, s11 = 0ULL;
            #pragma unroll
            for (int i = 0; i < 13; i++) {
                const ulonglong2 e0 = E0[i], e1 = E1[i];
                const ulonglong2 v0 = V0[i], v1 = V1[i];
                s00 = ffma2(e0.x, v0.x, s00); s00 = ffma2(e0.y, v0.y, s00);
                s01 = ffma2(e0.x, v1.x, s01); s01 = ffma2(e0.y, v1.y, s01);
                s10 = ffma2(e1.x, v0.x, s10); s10 = ffma2(e1.y, v0.y, s10);
                s11 = ffma2(e1.x, v1.x, s11); s11 = ffma2(e1.y, v1.y, s11);
            }
            sA[r0 * DP + d0] = unpack_add(s00);
            sA[r1 * DP + d0] = unpack_add(s10);
            if (d1 < DD) {
                sA[r0 * DP + d1] = unpack_add(s01);
                sA[r1 * DP + d1] = unpack_add(s11);
            }
        } else {
            const int r = idx - 150;
            const ulonglong2* E = (const ulonglong2*)&sE[r * NTOKP];
            unsigned long long z0 = 0ULL, z1 = 0ULL;
            #pragma unroll
            for (int i = 0; i < 13; i++) {
                const ulonglong2 e = E[i];
                z0 = add2(z0, e.x);
                z1 = add2(z1, e.y);
            }
            sZinv[r] = 1.f / (851.f + unpack_add(add2(z0, z1)));
        }
    }
    __syncthreads();

    // ================= E: Wo proj + residual, tiled 2 rows (25x11) ===============
    for (int idx = tid; idx < 275; idx += NT) {
        const int rp = idx / 11, d = idx - rp * 11;
        const int r0 = rp * 2, r1 = r0 + 1;
        const ulonglong2* W = (const ulonglong2*)&sWo[d * DP];
        const ulonglong2 w0 = W[0], w1 = W[1], w2 = W[2];
        const float s0 = dot12p(&sA[r0 * DP], (const float*)W);
        const float s1 = dot12r(((const ulonglong2*)&sA[r1 * DP])[0],
                                ((const ulonglong2*)&sA[r1 * DP])[1],
                                ((const ulonglong2*)&sA[r1 * DP])[2], w0, w1, w2);
        sR[r0 * DP + d] = sX[r0 * DP + d] + s0 * sZinv[r0];
        sR[r1 * DP + d] = sX[r1 * DP + d] + s1 * sZinv[r1];
    }
    __syncthreads();

    // ---- LayerNorm1 (50 threads) ----
    if (tid < 50) {
        float m = 0.f;
        #pragma unroll
        for (int d = 0; d < DD; d++) m += sR[tid * DP + d];
        m *= (1.f / 11.f);
        float v = 0.f;
        #pragma unroll
        for (int d = 0; d < DD; d++) { const float t = sR[tid * DP + d] - m; v += t * t; }
        const float rstd = rsqrtf(v * (1.f / 11.f) + 1e-5f);
        #pragma unroll
        for (int d = 0; d < DD; d++)
            sX1[tid * DP + d] = (sR[tid * DP + d] - m) * rstd * sLn1[d];
        sX1[tid * DP + DD] = 0.f;
    }
    __syncthreads();

    // ================= F: FF1 + relu, tiled 2 rows x 4 f (25x16) =================
    for (int idx = tid; idx < 25 * 16; idx += NT) {
        const int rp = idx / 16, ft = idx - rp * 16;
        const int r0 = rp * 2, r1 = r0 + 1;
        const ulonglong2* X0 = (const ulonglong2*)&sX1[r0 * DP];
        const ulonglong2* X1p = (const ulonglong2*)&sX1[r1 * DP];
        const ulonglong2 a0 = X0[0], a1 = X0[1], a2 = X0[2];
        const ulonglong2 b0 = X1p[0], b1 = X1p[1], b2 = X1p[2];
        #pragma unroll 1
        for (int i = 0; i < 4; i++) {
            const int f = ft * 4 + i;
            const ulonglong2* W = (const ulonglong2*)&sW1[f * DP];
            const ulonglong2 w0 = W[0], w1 = W[1], w2 = W[2];
            sH[r0 * FFP + f] = fmaxf(dot12r(a0, a1, a2, w0, w1, w2), 0.f);
            sH[r1 * FFP + f] = fmaxf(dot12r(b0, b1, b2, w0, w1, w2), 0.f);
        }
    }
    __syncthreads();

    // ================= G: FF2 + residual, tiled 2 rows x 2 d (25x6) ==============
    for (int idx = tid; idx < 150; idx += NT) {
        const int rp = idx / 6, dt = idx - rp * 6;
        const int r0 = rp * 2, r1 = r0 + 1;
        const int d0 = dt * 2, d1 = d0 + 1;
        const ulonglong2* H0 = (const ulonglong2*)&sH[r0 * FFP];
        const ulonglong2* H1 = (const ulonglong2*)&sH[r1 * FFP];
        const ulonglong2* W0 = (const ulonglong2*)&sW2[d0 * FFP];
        const ulonglong2* W1p = (const ulonglong2*)&sW2[((d1 < DD) ? d1 : d0) * FFP];
        unsigned long long s00 = 0ULL, s01 = 0ULL, s10 = 0ULL, s11 = 0ULL;
        #pragma unroll
        for (int i = 0; i < 16; i++) {
            const ulonglong2 h0 = H0[i], h1 = H1[i];
            const ulonglong2 w0 = W0[i], w1 = W1p[i];
            s00 = ffma2(h0.x, w0.x, s00); s00 = ffma2(h0.y, w0.y, s00);
            s01 = ffma2(h0.x, w1.x, s01); s01 = ffma2(h0.y, w1.y, s01);
            s10 = ffma2(h1.x, w0.x, s10); s10 = ffma2(h1.y, w0.y, s10);
            s11 = ffma2(h1.x, w1.x, s11); s11 = ffma2(h1.y, w1.y, s11);
        }
        sR[r0 * DP + d0] = sX1[r0 * DP + d0] + unpack_add(s00);
        sR[r1 * DP + d0] = sX1[r1 * DP + d0] + unpack_add(s10);
        if (d1 < DD) {
            sR[r0 * DP + d1] = sX1[r0 * DP + d1] + unpack_add(s01);
            sR[r1 * DP + d1] = sX1[r1 * DP + d1] + unpack_add(s11);
        }
    }
    __syncthreads();

    // ---- LayerNorm2 (50 threads) -> sO ----
    if (tid < 50) {
        float m = 0.f;
        #pragma unroll
        for (int d = 0; d < DD; d++) m += sR[tid * DP + d];
        m *= (1.f / 11.f);
        float v = 0.f;
        #pragma unroll
        for (int d = 0; d < DD; d++) { const float t = sR[tid * DP + d] - m; v += t * t; }
        const float rstd = rsqrtf(v * (1.f / 11.f) + 1e-5f);
        #pragma unroll
        for (int d = 0; d < DD; d++)
            sO[tid * DP + d] = (sR[tid * DP + d] - m) * rstd * sLn2[d];
    }
    __syncthreads();

    // ================= H: output (broadcast fill + window overwrite) =============
    float* ob = out + b * (10 * SEQ);
    for (int idx = tid; idx < 10 * (SEQ / 4); idx += NT) {
        const int c = idx / (SEQ / 4), q = idx - c * (SEQ / 4);
        const float z = sO[NTOK * DP + c];
        ((float4*)(ob + c * SEQ))[q] = make_float4(z, z, z, z);
    }
    __syncthreads();
    for (int idx = tid; idx < 10 * NTOK; idx += NT) {
        const int c = idx / NTOK, w = idx - c * NTOK;
        const int i = w / 7, j = w - i * 7;
        ob[c * SEQ + i * 30 + j] = sO[w * DP + c];
    }
}

extern "C" void kernel_launch(void* const* d_in, const int* in_sizes, int n_in,
                              void* d_out, int out_size) {
    const float* x    = (const float*)d_in[0];
    const float* Wqkv = (const float*)d_in[1];
    const float* Wo   = (const float*)d_in[2];
    const float* W1   = (const float*)d_in[3];
    const float* W2   = (const float*)d_in[4];
    const float* ln1  = (const float*)d_in[5];
    const float* ln2  = (const float*)d_in[6];
    float* out = (float*)d_out;
    pve_kernel<<<256, NT>>>(x, Wqkv, Wo, W1, W2, ln1, ln2, out);
}